// round 5
// baseline (speedup 1.0000x reference)
#include <cuda_runtime.h>
#include <cstdint>
#include <cstddef>

#define H 512
#define W 512
#define C 128
#define TI 16
#define TJ 16
// weights smem: [16 i][16 j][64 t], i-stride padded 1024 -> 1032 (== 8 mod 32)
#define WISTRIDE 1032
#define W3_FLOATS (16 * WISTRIDE)        // 16512
// x halo smem per pass: 32 channels as [8 chg][529 pix][4 ch]
#define XCHUNK 2116                      // 529*4; mod 32 == 4 -> 8 chgs spread all banks
#define XBUF (8 * XCHUNK)                // 16928 floats per buffer
#define SMEM_FLOATS (W3_FLOATS + 2 * XBUF + 529 + 256)
#define SMEM_BYTES (SMEM_FLOATS * 4)     // 204,612 B

typedef unsigned long long ull;

__device__ __forceinline__ ull pack2(float a, float b) {
    ull r; asm("mov.b64 %0, {%1, %2};" : "=l"(r) : "f"(a), "f"(b)); return r;
}
__device__ __forceinline__ void fma2(ull& d, ull a, ull b) {
    asm("fma.rn.f32x2 %0, %1, %2, %0;" : "+l"(d) : "l"(a), "l"(b));
}
__device__ __forceinline__ float2 unpack2(ull v) {
    float2 f; asm("mov.b64 {%0, %1}, %2;" : "=f"(f.x), "=f"(f.y) : "l"(v)); return f;
}
__device__ __forceinline__ void cp_async16(float* smem_dst, const float* gsrc, bool pred) {
    uint32_t s = (uint32_t)__cvta_generic_to_shared(smem_dst);
    int sz = pred ? 16 : 0;
    asm volatile("cp.async.cg.shared.global [%0], [%1], 16, %2;\n"
                 :: "r"(s), "l"(gsrc), "r"(sz));
}
__device__ __forceinline__ void cp_async4(float* smem_dst, const float* gsrc, bool pred) {
    uint32_t s = (uint32_t)__cvta_generic_to_shared(smem_dst);
    int sz = pred ? 4 : 0;
    asm volatile("cp.async.ca.shared.global [%0], [%1], 4, %2;\n"
                 :: "r"(s), "l"(gsrc), "r"(sz));
}
__device__ __forceinline__ void cp_commit() {
    asm volatile("cp.async.commit_group;\n" ::: "memory");
}
template <int N> __device__ __forceinline__ void cp_wait() {
    asm volatile("cp.async.wait_group %0;\n" :: "n"(N) : "memory");
}

// ---- stage one 32-channel x halo pass into xbuf[8 chg][529 pix][4] ----
// 8 consecutive lanes cover one pixel's 32 channels (128 B contiguous gmem).
__device__ __forceinline__ void stage_x(float* xbuf, const float* __restrict__ gx,
                                        int bi, int bj, int pass, int tid) {
    const int cbase = pass * 32;
    #pragma unroll 4
    for (int u = tid; u < 529 * 8; u += 512) {
        int q = u & 7, pix = u >> 3;
        int hr = pix / 23, hc = pix - hr * 23;
        int gr = bi + hr - 3, gcl = bj + hc - 3;
        bool ok = ((unsigned)gr < H) && ((unsigned)gcl < W);
        const float* src = ok
            ? gx + (((size_t)gr * W + gcl) * C + cbase + q * 4)
            : gx;
        cp_async16(xbuf + q * XCHUNK + pix * 4, src, ok);
    }
}

// ---- compute one pass: 1 row x 8 cols x 4 ch x 4 taps(p) per thread ----
// Each thread handles p in [ph*4, ph*4+4); partner thread (lane ^ 8) has the
// other half; partials combined via shfl.xor before the store.
__device__ __forceinline__ void compute_pass(const float* __restrict__ xbuf,
                                             const float* __restrict__ w3,
                                             const float* __restrict__ inv,
                                             float* __restrict__ gout,
                                             int bi, int bj, int cbase,
                                             int row, int j0, int chg, int ph) {
    ull acc[8][2];
    #pragma unroll
    for (int j = 0; j < 8; ++j) { acc[j][0] = 0ull; acc[j][1] = 0ull; }

    const float* xr0 = xbuf + chg * XCHUNK + (((row + ph * 4) * 23 + j0) * 4);
    const float* wp0 = w3 + row * WISTRIDE + j0 * 64 + ph * 32;

    #pragma unroll
    for (int pp = 0; pp < 4; ++pp) {
        // load the 15-position halo row (4 ch each) into registers
        ull xv[15][2];
        const float* xr = xr0 + (pp * 23) * 4;
        #pragma unroll
        for (int t = 0; t < 15; ++t) {
            ulonglong2 v = *(const ulonglong2*)(xr + t * 4);
            xv[t][0] = v.x; xv[t][1] = v.y;
        }
        #pragma unroll
        for (int j = 0; j < 8; ++j) {
            #pragma unroll
            for (int qg = 0; qg < 2; ++qg) {
                float4 w4 = *(const float4*)(wp0 + j * 64 + pp * 8 + qg * 4);
                const int q0 = qg * 4;
                ull w0 = pack2(w4.x, w4.x);
                ull w1 = pack2(w4.y, w4.y);
                ull w2 = pack2(w4.z, w4.z);
                ull w3p = pack2(w4.w, w4.w);
                fma2(acc[j][0], xv[j + q0 + 0][0], w0);
                fma2(acc[j][1], xv[j + q0 + 0][1], w0);
                fma2(acc[j][0], xv[j + q0 + 1][0], w1);
                fma2(acc[j][1], xv[j + q0 + 1][1], w1);
                fma2(acc[j][0], xv[j + q0 + 2][0], w2);
                fma2(acc[j][1], xv[j + q0 + 2][1], w2);
                fma2(acc[j][0], xv[j + q0 + 3][0], w3p);
                fma2(acc[j][1], xv[j + q0 + 3][1], w3p);
            }
        }
    }

    // ---- reduce across ph (lane ^ 8), normalize, store ----
    // After reduction every lane holds the full sum for all 8 j; the two ph
    // half-groups store disjoint j-halves so all 32 lanes issue float4 STG.
    float2 sum[8][2];
    #pragma unroll
    for (int j = 0; j < 8; ++j) {
        #pragma unroll
        for (int k = 0; k < 2; ++k) {
            ull other = __shfl_xor_sync(0xffffffffu, acc[j][k], 8);
            float2 a = unpack2(acc[j][k]);
            float2 b = unpack2(other);
            sum[j][k] = make_float2(a.x + b.x, a.y + b.y);
        }
    }
    #pragma unroll
    for (int jl = 0; jl < 4; ++jl) {
        const int j = ph * 4 + jl;
        float s = inv[row * 16 + j0 + j];
        float4 v = make_float4(sum[j][0].x * s, sum[j][0].y * s,
                               sum[j][1].x * s, sum[j][1].y * s);
        *(float4*)(gout + (((size_t)(bi + row) * W + (bj + j0 + j)) * C
                           + cbase + chg * 4)) = v;
    }
}

__global__ __launch_bounds__(512, 1) void cell_att_kernel(
    const float* __restrict__ gx,   // [H][W][C]
    const float* __restrict__ gw,   // [H][W][64]
    const float* __restrict__ gc,   // [H][W]
    float* __restrict__ gout)       // [H][W][C]
{
    extern __shared__ float smem[];
    float* w3  = smem;                 // [16 i][16 j][64 t], i-stride 1032
    float* xs0 = w3 + W3_FLOATS;
    float* xs1 = xs0 + XBUF;
    float* ch  = xs1 + XBUF;           // 23x23 cnts halo
    float* inv = ch + 529;             // 256 per-pixel 1/(tcnt+1e-6)

    const int tid = threadIdx.x;
    const int chg = tid & 7;           // channel quad within pass (4 ch)
    const int ph  = (tid >> 3) & 1;    // tap-half: p in [4ph, 4ph+4)
    const int cfg = tid >> 4;          // 0..31
    const int row = cfg & 15;          // 0..15
    const int j0  = (cfg >> 4) * 8;    // 0 or 8
    const int bi = blockIdx.y * TI, bj = blockIdx.x * TJ;

    // ---- G0: weights (coalesced, natural layout) + cnts halo ----
    #pragma unroll 8
    for (int u = tid; u < 256 * 16; u += 512) {
        int quad = u & 15, px = u >> 4;
        int il = px >> 4, jl = px & 15;
        const float* src = gw + ((size_t)(bi + il) * W + (bj + jl)) * 64 + quad * 4;
        cp_async16(w3 + il * WISTRIDE + jl * 64 + quad * 4, src, true);
    }
    for (int u = tid; u < 529; u += 512) {
        int hr = u / 23, hc = u - hr * 23;
        int gr = bi + hr - 3, gcl = bj + hc - 3;
        bool ok = ((unsigned)gr < H) && ((unsigned)gcl < W);
        const float* src = ok ? gc + (size_t)gr * W + gcl : gc;
        cp_async4(ch + u, src, ok);
    }
    cp_commit();                       // G0
    stage_x(xs0, gx, bi, bj, 0, tid);
    cp_commit();                       // G1
    stage_x(xs1, gx, bi, bj, 1, tid);
    cp_commit();                       // G2

    cp_wait<2>();                      // G0 (weights + cnts) done
    __syncthreads();

    // ---- normalizer: inv = 1/(att(cnts)+1e-6), one pixel per thread ----
    if (tid < 256) {
        int il = tid >> 4, jl = tid & 15;
        const float* wpx = w3 + il * WISTRIDE + jl * 64;
        float s = 0.f;
        #pragma unroll
        for (int p = 0; p < 8; ++p)
            #pragma unroll
            for (int q = 0; q < 8; ++q)
                s += ch[(il + p) * 23 + (jl + q)] * wpx[p * 8 + q];
        inv[tid] = 1.0f / (s + 1e-6f);
    }

    cp_wait<1>();                      // G1 (x pass0) done
    __syncthreads();                   // inv + x0 visible to all
    compute_pass(xs0, w3, inv, gout, bi, bj, 0, row, j0, chg, ph);

    __syncthreads();                   // all readers done with xs0
    stage_x(xs0, gx, bi, bj, 2, tid);
    cp_commit();                       // G3
    cp_wait<1>();                      // G2 (x pass1) done
    __syncthreads();
    compute_pass(xs1, w3, inv, gout, bi, bj, 32, row, j0, chg, ph);

    __syncthreads();                   // all readers done with xs1
    stage_x(xs1, gx, bi, bj, 3, tid);
    cp_commit();                       // G4
    cp_wait<1>();                      // G3 (x pass2) done
    __syncthreads();
    compute_pass(xs0, w3, inv, gout, bi, bj, 64, row, j0, chg, ph);

    cp_wait<0>();                      // G4 (x pass3) done
    __syncthreads();
    compute_pass(xs1, w3, inv, gout, bi, bj, 96, row, j0, chg, ph);
}

extern "C" void kernel_launch(void* const* d_in, const int* in_sizes, int n_in,
                              void* d_out, int out_size) {
    const float* x0 = (const float*)d_in[0];
    const float* w  = (const float*)d_in[1];
    const float* c  = (const float*)d_in[2];
    float* out      = (float*)d_out;
    cudaFuncSetAttribute(cell_att_kernel,
                         cudaFuncAttributeMaxDynamicSharedMemorySize, SMEM_BYTES);
    dim3 grid(W / TJ, H / TI);
    cell_att_kernel<<<grid, 512, SMEM_BYTES>>>(x0, w, c, out);
}